// round 8
// baseline (speedup 1.0000x reference)
#include <cuda_runtime.h>

#define NT 64
typedef unsigned long long u64;

__device__ __forceinline__ u64 pk2(float x, float y) {
    u64 r; asm("mov.b64 %0,{%1,%2};" : "=l"(r) : "f"(x), "f"(y)); return r;
}
__device__ __forceinline__ void upk2(u64 v, float& x, float& y) {
    asm("mov.b64 {%0,%1},%2;" : "=f"(x), "=f"(y) : "l"(v));
}
__device__ __forceinline__ u64 ffma2(u64 a, u64 b, u64 c) {
    u64 d; asm("fma.rn.f32x2 %0,%1,%2,%3;" : "=l"(d) : "l"(a), "l"(b), "l"(c)); return d;
}

// packed butterfly over pair-index bit B
template <int B>
__device__ __forceinline__ void vstage(u64* v, float t) {
    u64 tp = pk2(t, t), tn = pk2(-t, -t);
#pragma unroll
    for (int a = 0; a < 32; ++a)
        if (!(a & (1 << B))) {
            u64 A = v[a], Bv = v[a | (1 << B)];
            v[a]            = ffma2(tn, Bv, A);
            v[a | (1 << B)] = ffma2(tp, A, Bv);
        }
}

// scalar component stage (bit 0 of element index lives in the f32x2 lanes)
__device__ __forceinline__ void cstage(u64* v, float t) {
#pragma unroll
    for (int a = 0; a < 32; ++a) {
        float x, y; upk2(v[a], x, y);
        float nx = fmaf(-t, y, x);
        float ny = fmaf( t, x, y);
        v[a] = pk2(nx, ny);
    }
}

// entangling-map destination high block: i[6..11] = f(m = s[6..11])  (compile-time)
__device__ __forceinline__ constexpr int Bmap(int m) {
    int m0 = m & 1, m1 = (m >> 1) & 1, m2 = (m >> 2) & 1;
    int m3 = (m >> 3) & 1, m4 = (m >> 4) & 1, m5 = (m >> 5) & 1;
    return (m0 ^ m1) | ((m1 ^ m2 ^ m3) << 1) | ((m2 ^ m3) << 2)
         | ((m3 ^ m4 ^ m5) << 3) | ((m4 ^ m5) << 4) | (m5 << 5);
}

// P1 address (floats) for state element s: store at destination i = M^{-1}(s)
__device__ __forceinline__ int embedAddr(int s) {
    int s0 = s & 1, s1 = (s >> 1) & 1, s2 = (s >> 2) & 1, s3 = (s >> 3) & 1;
    int s4 = (s >> 4) & 1, s5 = (s >> 5) & 1, s6 = (s >> 6) & 1, s7 = (s >> 7) & 1;
    int s8 = (s >> 8) & 1, s9 = (s >> 9) & 1, s10 = (s >> 10) & 1, s11 = (s >> 11) & 1;
    int lo = (s0 ^ s1) | ((s1 ^ s2 ^ s3) << 1) | ((s2 ^ s3) << 2)
           | ((s3 ^ s4 ^ s5) << 3) | ((s4 ^ s5) << 4) | ((s5 ^ s6 ^ s7) << 5);
    int hi = (s6 ^ s7) | ((s7 ^ s8 ^ s9) << 1) | ((s8 ^ s9) << 2)
           | ((s9 ^ s10 ^ s11) << 3) | ((s10 ^ s11) << 4) | (s11 << 5);
    return hi * 68 + lo;
}

__global__ void __launch_bounds__(NT, 9)
qsim_kernel(const float* __restrict__ feats,
            const float* __restrict__ qp,
            float* __restrict__ out)
{
    // padded state buffer: 64 blocks x 68 floats (pad-4 rotates banks additively)
    __shared__ float buf[64 * 68];
    __shared__ float tt[240];
    __shared__ float wred[2], gred[2];
    __shared__ float oscale_s;
    __shared__ float rsum[2][12];

    const int u    = threadIdx.x;   // 0..63
    const int lane = u & 31;
    const int b    = blockIdx.x;

    // tan table + global cos product (cos factors -> output scale G^2)
    float gpart = 1.0f;
    for (int i = u; i < 240; i += NT) {
        float s, c; sincosf(0.5f * qp[12 + i], &s, &c);
        tt[i] = s / c; gpart *= c;
    }
#pragma unroll
    for (int o = 16; o; o >>= 1) gpart *= __shfl_xor_sync(~0u, gpart, o);
    if (lane == 0) gred[u >> 5] = gpart;

    // embedding, scattered pre-entangled for layer 0 (P1 layout)
    const float2* f2 = reinterpret_cast<const float2*>(feats + (size_t)b * 2048);
    const float PIO2 = 1.5707963267948966f;
    float acc = 8.0f;
#pragma unroll
    for (int v = 0; v < 16; ++v) {
        int p = v * 64 + u;
        float2 x = f2[p];
        float y0 = tanhf(x.x) * PIO2;
        float y1 = tanhf(x.y) * PIO2;
        acc += y0 * y0 + y1 * y1;
        buf[embedAddr(2 * p)]     = y0;
        buf[embedAddr(2 * p + 1)] = y1;
    }
#pragma unroll
    for (int v = 16; v < 32; ++v) {
        int p = v * 64 + u;
        buf[embedAddr(2 * p)]     = 0.5f;
        buf[embedAddr(2 * p + 1)] = 0.5f;
    }
#pragma unroll
    for (int o = 16; o; o >>= 1) acc += __shfl_xor_sync(~0u, acc, o);
    if (lane == 0) wred[u >> 5] = acc;
    __syncthreads();
    if (u == 0) {
        float G = gred[0] * gred[1];
        oscale_s = (G * G) / (wred[0] + wred[1]);
    }

    // per-thread bases (all loop addressing = base + compile-time imm)
    float* pld = buf + u * 68;   // linear block read, both passes
    float* ps1 = buf + u;        // pass-1 column store: + i_lo*68
    int u0 = u & 1, u1 = (u >> 1) & 1, u2b = (u >> 2) & 1;
    int u3 = (u >> 3) & 1, u4 = (u >> 4) & 1, u5 = (u >> 5) & 1;
    int Off = (u0 ^ u1) | ((u1 ^ u2b ^ u3) << 1) | ((u2b ^ u3) << 2)
            | ((u3 ^ u4 ^ u5) << 3) | ((u4 ^ u5) << 4) | (u5 << 5);
    float* pp0 = buf + Off;          // pass-2 store base, parity 0
    float* pp1 = buf + (Off ^ 32);   // pass-2 store base, parity 1
    __syncthreads();

#pragma unroll 1
    for (int L = 0; L < 20; ++L) {
        const float* tc = &tt[L * 12];

        // ===== pass 1: linear load (E already applied by prev store) + RY bits 0..5 =====
        u64 vr[32];
        {
            float t10 = tc[10];
            u64 tn = pk2(-t10, -t10), tp = pk2(t10, t10);
#pragma unroll
            for (int g = 0; g < 16; ++g) {
                float4 f = *reinterpret_cast<const float4*>(pld + 4 * g);
                u64 lo = pk2(f.x, f.y), hi = pk2(f.z, f.w);
                vr[2 * g]     = ffma2(tn, hi, lo);   // fold q10 (bit 1)
                vr[2 * g + 1] = ffma2(tp, lo, hi);
            }
        }
        cstage(vr, tc[11]);        // q11 = bit 0 (component)
        vstage<1>(vr, tc[9]);      // bit 2
        vstage<2>(vr, tc[8]);
        vstage<3>(vr, tc[7]);
        vstage<4>(vr, tc[6]);      // bit 5
        __syncthreads();           // all loads done before in-place overwrite
#pragma unroll
        for (int j = 0; j < 32; ++j) {
            float x, y; upk2(vr[j], x, y);
            ps1[(2 * j) * 68]     = x;     // T layout: block=i_lo, offset=u
            ps1[(2 * j + 1) * 68] = y;
        }
        __syncthreads();

        // ===== pass 2: linear load (transpose) + RY bits 6..11 =====
        u64 vp[32];
        {
            float t4 = tc[4];
            u64 tn = pk2(-t4, -t4), tp = pk2(t4, t4);
#pragma unroll
            for (int g = 0; g < 16; ++g) {
                float4 f = *reinterpret_cast<const float4*>(pld + 4 * g);
                u64 lo = pk2(f.x, f.y), hi = pk2(f.z, f.w);
                vp[2 * g]     = ffma2(tn, hi, lo);   // fold q4 (bit 7)
                vp[2 * g + 1] = ffma2(tp, lo, hi);
            }
        }
        cstage(vp, tc[5]);         // q5 = bit 6 (component)
        vstage<1>(vp, tc[3]);      // bit 8
        vstage<2>(vp, tc[2]);
        vstage<3>(vp, tc[1]);
        vstage<4>(vp, tc[0]);      // bit 11

        if (L < 19) {
            __syncthreads();       // all pass-2 loads done before scatter
#pragma unroll
            for (int j = 0; j < 32; ++j) {
                float x, y; upk2(vp[j], x, y);
                // x: m=2j (s6=0): parity p = 0 ^ j0 ; y: m=2j+1: p = 1 ^ j0
                if (j & 1) { pp1[Bmap(2 * j) * 68] = x; pp0[Bmap(2 * j + 1) * 68] = y; }
                else       { pp0[Bmap(2 * j) * 68] = x; pp1[Bmap(2 * j + 1) * 68] = y; }
            }
            __syncthreads();
        } else {
            // ===== expvals straight from registers =====
            // component = bit6 (q5); pair bits j0..j4 = bits 7..11 (q4..q0); u = bits 0..5
            float S = 0.f, Ty = 0.f, T0 = 0.f, T1 = 0.f, T2 = 0.f, T3 = 0.f, T4 = 0.f;
#pragma unroll
            for (int a = 0; a < 32; ++a) {
                float x, y; upk2(vp[a], x, y);
                float px = x * x, py = y * y, ps = px + py;
                S += ps; Ty += py;
                if (a & 1)  T0 += ps;
                if (a & 2)  T1 += ps;
                if (a & 4)  T2 += ps;
                if (a & 8)  T3 += ps;
                if (a & 16) T4 += ps;
            }
            float val[12];
            val[0] = S - 2.f * T4;   // q0 = bit 11 = j4
            val[1] = S - 2.f * T3;
            val[2] = S - 2.f * T2;
            val[3] = S - 2.f * T1;
            val[4] = S - 2.f * T0;   // q4 = bit 7 = j0
            val[5] = S - 2.f * Ty;   // q5 = bit 6 = component
#pragma unroll
            for (int q = 6; q < 12; ++q)
                val[q] = ((u >> (11 - q)) & 1) ? -S : S;
#pragma unroll
            for (int q = 0; q < 12; ++q) {
#pragma unroll
                for (int o = 16; o; o >>= 1)
                    val[q] += __shfl_xor_sync(~0u, val[q], o);
            }
            if (lane == 0) {
#pragma unroll
                for (int q = 0; q < 12; ++q) rsum[u >> 5][q] = val[q];
            }
        }
    }

    __syncthreads();
    if (u < 12) {
        out[(size_t)b * 12 + u] = (rsum[0][u] + rsum[1][u]) * oscale_s;
    }
}

extern "C" void kernel_launch(void* const* d_in, const int* in_sizes, int n_in,
                              void* d_out, int out_size) {
    const float* feats = (const float*)d_in[0];
    const float* qp    = (const float*)d_in[1];
    float* out         = (float*)d_out;
    qsim_kernel<<<4096, NT>>>(feats, qp, out);
}

// round 9
// speedup vs baseline: 1.0313x; 1.0313x over previous
#include <cuda_runtime.h>

#define NT 64
typedef unsigned long long u64;

__device__ __forceinline__ u64 pk2(float x, float y) {
    u64 r; asm("mov.b64 %0,{%1,%2};" : "=l"(r) : "f"(x), "f"(y)); return r;
}
__device__ __forceinline__ void upk2(u64 v, float& x, float& y) {
    asm("mov.b64 {%0,%1},%2;" : "=f"(x), "=f"(y) : "l"(v));
}
__device__ __forceinline__ u64 ffma2(u64 a, u64 b, u64 c) {
    u64 d; asm("fma.rn.f32x2 %0,%1,%2,%3;" : "=l"(d) : "l"(a), "l"(b), "l"(c)); return d;
}

// packed butterfly over pair-index bit B
template <int B>
__device__ __forceinline__ void vstage(u64* v, float t) {
    u64 tp = pk2(t, t), tn = pk2(-t, -t);
#pragma unroll
    for (int a = 0; a < 32; ++a)
        if (!(a & (1 << B))) {
            u64 A = v[a], Bv = v[a | (1 << B)];
            v[a]            = ffma2(tn, Bv, A);
            v[a | (1 << B)] = ffma2(tp, A, Bv);
        }
}

// component stage (element-index bit 0 lives in the f32x2 lanes)
__device__ __forceinline__ void cstage(u64* v, float t) {
#pragma unroll
    for (int a = 0; a < 32; ++a) {
        float x, y; upk2(v[a], x, y);
        v[a] = pk2(fmaf(-t, y, x), fmaf(t, x, y));
    }
}

// register-pair index for pass-1 load row-pair q: a = (f0^{-1}(2q)) >> 1
__device__ __forceinline__ constexpr int AQ(int q) {
    int q0 = q & 1, q1 = (q >> 1) & 1, q2 = (q >> 2) & 1, q3 = (q >> 3) & 1, q4 = (q >> 4) & 1;
    return (q0 ^ q1 ^ q2) | ((q1 ^ q2) << 1) | ((q2 ^ q3 ^ q4) << 2)
         | ((q3 ^ q4) << 3) | (q4 << 4);
}

#define PITCH 68

__global__ void __launch_bounds__(NT, 10)
qsim_kernel(const float* __restrict__ feats,
            const float* __restrict__ qp,
            float* __restrict__ out)
{
    // layout T: element (i_lo, i_hi) at i_lo*PITCH + i_hi  (pad 68 -> bank rot by 4/row)
    __shared__ float buf[64 * PITCH];
    __shared__ float tt[240];
    __shared__ float wred[2], gred[2];
    __shared__ float oscale_s;
    __shared__ float rsum[2][12];

    const int u    = threadIdx.x;   // 0..63
    const int lane = u & 31;
    const int b    = blockIdx.x;

    // tan table + global cos product (cos factors -> output scale G^2)
    float gpart = 1.0f;
    for (int i = u; i < 240; i += NT) {
        float s, c; sincosf(0.5f * qp[12 + i], &s, &c);
        tt[i] = s / c; gpart *= c;
    }
#pragma unroll
    for (int o = 16; o; o >>= 1) gpart *= __shfl_xor_sync(~0u, gpart, o);
    if (lane == 0) gred[u >> 5] = gpart;

    // embedding: raw state into T layout (elem s at (s&63)*PITCH + (s>>6))
    const float2* f2 = reinterpret_cast<const float2*>(feats + (size_t)b * 2048);
    const float PIO2 = 1.5707963267948966f;
    float acc = 8.0f;
#pragma unroll
    for (int v = 0; v < 16; ++v) {
        int p = v * 64 + u;
        float2 x = f2[p];
        float y0 = tanhf(x.x) * PIO2;
        float y1 = tanhf(x.y) * PIO2;
        acc += y0 * y0 + y1 * y1;
        int s = 2 * p;
        buf[(s & 63) * PITCH + (s >> 6)]       = y0;
        buf[((s + 1) & 63) * PITCH + (s >> 6)] = y1;
    }
#pragma unroll
    for (int v = 16; v < 32; ++v) {
        int s = 2 * (v * 64 + u);
        buf[(s & 63) * PITCH + (s >> 6)]       = 0.5f;
        buf[((s + 1) & 63) * PITCH + (s >> 6)] = 0.5f;
    }
#pragma unroll
    for (int o = 16; o; o >>= 1) acc += __shfl_xor_sync(~0u, acc, o);
    if (lane == 0) wred[u >> 5] = acc;
    __syncthreads();
    if (u == 0) {
        float G = gred[0] * gred[1];
        oscale_s = (G * G) / (wred[0] + wred[1]);
    }

    // per-thread constants
    // i_hi = H(u) = Mhi^{-1}(u): h0=u0^u1, h1=u1^u2^u3, h2=u2^u3, h3=u3^u4^u5, h4=u4^u5, h5=u5
    int u0 = u & 1, u1 = (u >> 1) & 1, u2b = (u >> 2) & 1;
    int u3 = (u >> 3) & 1, u4 = (u >> 4) & 1, u5 = (u >> 5) & 1;
    int Hh = (u0 ^ u1) | ((u1 ^ u2b ^ u3) << 1) | ((u2b ^ u3) << 2)
           | ((u3 ^ u4 ^ u5) << 3) | ((u4 ^ u5) << 4) | (u5 << 5);
    int e = u0 ^ u1;                         // i6 of this thread's dst block
    const float* pL = buf + u;               // pass-1 load base (col u, + m*PITCH imm)
    float* B0 = buf + Hh + (e ? 32 * PITCH : 0);            // pass-1 store, rows 0..31
    float* B1 = buf + Hh + (e ? 0 : 32 * PITCH);            // pass-1 store, rows 32..63
    float* pld = buf + u * PITCH;            // pass-2 base (in-place)
    float esgn = e ? -1.0f : 1.0f;

#pragma unroll 1
    for (int L = 0; L < 20; ++L) {
        const float* tc = &tt[L * 12];

        // ===== pass 1: entangling gather (addressing-free) + RY qubits 11..6 =====
        u64 vr[32];
        {
            float t11 = tc[11];
            u64 tm = pk2(-t11, t11);
#pragma unroll
            for (int q = 0; q < 32; ++q) {
                float A = pL[(2 * q) * PITCH];
                float Bv = pL[(2 * q + 1) * PITCH];
                u64 ab = pk2(A, Bv), ba = pk2(Bv, A);
                // role: even row holds comp0 iff (q&1)==0
                vr[AQ(q)] = (q & 1) ? ffma2(tm, ab, ba) : ffma2(tm, ba, ab);
            }
        }
        vstage<0>(vr, tc[10]);
        vstage<1>(vr, tc[9]);
        vstage<2>(vr, tc[8]);
        vstage<3>(vr, tc[7]);
        vstage<4>(vr, esgn * tc[6]);   // e-swapped pairing on bit5 => R(-t)
        __syncthreads();               // all gathers done before rows are overwritten
#pragma unroll
        for (int a = 0; a < 16; ++a) {
            float x, y; upk2(vr[a], x, y);
            B0[(2 * a) * PITCH]     = x;
            B0[(2 * a + 1) * PITCH] = y;
        }
#pragma unroll
        for (int a = 16; a < 32; ++a) {
            float x, y; upk2(vr[a], x, y);
            B1[(2 * a - 32) * PITCH] = x;
            B1[(2 * a - 31) * PITCH] = y;
        }
        __syncthreads();

        // ===== pass 2: linear in-place, RY qubits 5..0 =====
        u64 vp[32];
        {
            float t4 = tc[4];
            u64 tn = pk2(-t4, -t4), tp = pk2(t4, t4);
#pragma unroll
            for (int g = 0; g < 16; ++g) {
                float4 f = *reinterpret_cast<const float4*>(pld + 4 * g);
                u64 lo = pk2(f.x, f.y), hi = pk2(f.z, f.w);
                vp[2 * g]     = ffma2(tn, hi, lo);   // fold q4 (pair-bit 0)
                vp[2 * g + 1] = ffma2(tp, lo, hi);
            }
        }
        cstage(vp, tc[5]);       // qubit 5 = component (i6)
        vstage<1>(vp, tc[3]);
        vstage<2>(vp, tc[2]);
        vstage<3>(vp, tc[1]);
        vstage<4>(vp, tc[0]);

        if (L < 19) {
#pragma unroll
            for (int g = 0; g < 16; ++g) {
                float x0, y0, x1, y1;
                upk2(vp[2 * g], x0, y0);
                upk2(vp[2 * g + 1], x1, y1);
                *reinterpret_cast<float4*>(pld + 4 * g) = make_float4(x0, y0, x1, y1);
            }
            __syncthreads();
        } else {
            // ===== expvals from registers =====
            // component = i6 (q5); pair bits b0..b4 = i7..i11 (q4..q0); u = i0..i5 (q11..q6)
            float S = 0.f, Ty = 0.f, T0 = 0.f, T1 = 0.f, T2 = 0.f, T3 = 0.f, T4 = 0.f;
#pragma unroll
            for (int a = 0; a < 32; ++a) {
                float x, y; upk2(vp[a], x, y);
                float px = x * x, py = y * y, ps = px + py;
                S += ps; Ty += py;
                if (a & 1)  T0 += ps;
                if (a & 2)  T1 += ps;
                if (a & 4)  T2 += ps;
                if (a & 8)  T3 += ps;
                if (a & 16) T4 += ps;
            }
            float val[12];
            val[0] = S - 2.f * T4;
            val[1] = S - 2.f * T3;
            val[2] = S - 2.f * T2;
            val[3] = S - 2.f * T1;
            val[4] = S - 2.f * T0;
            val[5] = S - 2.f * Ty;
#pragma unroll
            for (int q = 6; q < 12; ++q)
                val[q] = ((u >> (11 - q)) & 1) ? -S : S;
#pragma unroll
            for (int q = 0; q < 12; ++q) {
#pragma unroll
                for (int o = 16; o; o >>= 1)
                    val[q] += __shfl_xor_sync(~0u, val[q], o);
            }
            if (lane == 0) {
#pragma unroll
                for (int q = 0; q < 12; ++q) rsum[u >> 5][q] = val[q];
            }
        }
    }

    __syncthreads();
    if (u < 12) {
        out[(size_t)b * 12 + u] = (rsum[0][u] + rsum[1][u]) * oscale_s;
    }
}

extern "C" void kernel_launch(void* const* d_in, const int* in_sizes, int n_in,
                              void* d_out, int out_size) {
    const float* feats = (const float*)d_in[0];
    const float* qp    = (const float*)d_in[1];
    float* out         = (float*)d_out;
    qsim_kernel<<<4096, NT>>>(feats, qp, out);
}

// round 10
// speedup vs baseline: 1.0398x; 1.0082x over previous
#include <cuda_runtime.h>

#define NT 64
typedef unsigned long long u64;

__device__ __forceinline__ u64 pk2(float x, float y) {
    u64 r; asm("mov.b64 %0,{%1,%2};" : "=l"(r) : "f"(x), "f"(y)); return r;
}
__device__ __forceinline__ void upk2(u64 v, float& x, float& y) {
    asm("mov.b64 {%0,%1},%2;" : "=f"(x), "=f"(y) : "l"(v));
}
__device__ __forceinline__ u64 ffma2(u64 a, u64 b, u64 c) {
    u64 d; asm("fma.rn.f32x2 %0,%1,%2,%3;" : "=l"(d) : "l"(a), "l"(b), "l"(c)); return d;
}

// packed butterfly over pair-index bit B
template <int B>
__device__ __forceinline__ void vstage(u64* v, float t) {
    u64 tp = pk2(t, t), tn = pk2(-t, -t);
#pragma unroll
    for (int a = 0; a < 32; ++a)
        if (!(a & (1 << B))) {
            u64 A = v[a], Bv = v[a | (1 << B)];
            v[a]            = ffma2(tn, Bv, A);
            v[a | (1 << B)] = ffma2(tp, A, Bv);
        }
}

// register-pair index for pass-1 load row-pair q: a = (f0^{-1}(2q)) >> 1
__device__ __forceinline__ constexpr int AQ(int q) {
    int q0 = q & 1, q1 = (q >> 1) & 1, q2 = (q >> 2) & 1, q3 = (q >> 3) & 1, q4 = (q >> 4) & 1;
    return (q0 ^ q1 ^ q2) | ((q1 ^ q2) << 1) | ((q2 ^ q3 ^ q4) << 2)
         | ((q3 ^ q4) << 3) | (q4 << 4);
}

#define PITCH 68

__global__ void __launch_bounds__(NT, 11)
qsim_kernel(const float* __restrict__ feats,
            const float* __restrict__ qp,
            float* __restrict__ out)
{
    // layout T: element (i_lo, i_hi) at i_lo*PITCH + i_hi  (pad 68 -> bank rot by 4/row)
    __shared__ float buf[64 * PITCH];
    __shared__ float tt[240];
    __shared__ float wred[2], gred[2];
    __shared__ float oscale_s;
    __shared__ float rsum[2][12];

    const int u    = threadIdx.x;   // 0..63
    const int lane = u & 31;
    const int b    = blockIdx.x;

    // tan table + global cos product (cos factors -> output scale G^2)
    float gpart = 1.0f;
    for (int i = u; i < 240; i += NT) {
        float s, c; sincosf(0.5f * qp[12 + i], &s, &c);
        tt[i] = s / c; gpart *= c;
    }
#pragma unroll
    for (int o = 16; o; o >>= 1) gpart *= __shfl_xor_sync(~0u, gpart, o);
    if (lane == 0) gred[u >> 5] = gpart;

    // embedding: raw state into T layout (elem s at (s&63)*PITCH + (s>>6))
    const float2* f2 = reinterpret_cast<const float2*>(feats + (size_t)b * 2048);
    const float PIO2 = 1.5707963267948966f;
    float acc = 8.0f;
#pragma unroll
    for (int v = 0; v < 16; ++v) {
        int p = v * 64 + u;
        float2 x = f2[p];
        float y0 = tanhf(x.x) * PIO2;
        float y1 = tanhf(x.y) * PIO2;
        acc += y0 * y0 + y1 * y1;
        int s = 2 * p;
        buf[(s & 63) * PITCH + (s >> 6)]       = y0;
        buf[((s + 1) & 63) * PITCH + (s >> 6)] = y1;
    }
#pragma unroll
    for (int v = 16; v < 32; ++v) {
        int s = 2 * (v * 64 + u);
        buf[(s & 63) * PITCH + (s >> 6)]       = 0.5f;
        buf[((s + 1) & 63) * PITCH + (s >> 6)] = 0.5f;
    }
#pragma unroll
    for (int o = 16; o; o >>= 1) acc += __shfl_xor_sync(~0u, acc, o);
    if (lane == 0) wred[u >> 5] = acc;
    __syncthreads();
    if (u == 0) {
        float G = gred[0] * gred[1];
        oscale_s = (G * G) / (wred[0] + wred[1]);
    }

    // per-thread constants
    // i_hi = H(u) = Mhi^{-1}(u)
    int u0 = u & 1, u1 = (u >> 1) & 1, u2b = (u >> 2) & 1;
    int u3 = (u >> 3) & 1, u4 = (u >> 4) & 1, u5 = (u >> 5) & 1;
    int Hh = (u0 ^ u1) | ((u1 ^ u2b ^ u3) << 1) | ((u2b ^ u3) << 2)
           | ((u3 ^ u4 ^ u5) << 3) | ((u4 ^ u5) << 4) | (u5 << 5);
    int e = u0 ^ u1;                         // i6 of this thread's dst block
    const float* pL = buf + u;               // pass-1 load base (col u, + m*PITCH imm)
    float* B0 = buf + Hh + (e ? 32 * PITCH : 0);   // pass-1 store, rows 0..31
    float* B1 = buf + Hh + (e ? 0 : 32 * PITCH);   // pass-1 store, rows 32..63
    float* pld = buf + u * PITCH;            // pass-2 base (in-place)
    float esgn = e ? -1.0f : 1.0f;

#pragma unroll 1
    for (int L = 0; L < 20; ++L) {
        const float* tc = &tt[L * 12];

        // ===== pass 1: entangling gather (addressing-free) + RY qubits 11..6 =====
        u64 vr[32];
        {
            float t11 = tc[11];
            u64 tm = pk2(-t11, t11);
#pragma unroll
            for (int q = 0; q < 32; ++q) {
                float A = pL[(2 * q) * PITCH];
                float Bv = pL[(2 * q + 1) * PITCH];
                u64 ab = pk2(A, Bv), ba = pk2(Bv, A);
                // role: even row holds comp0 iff (q&1)==0
                vr[AQ(q)] = (q & 1) ? ffma2(tm, ab, ba) : ffma2(tm, ba, ab);
            }
        }
        vstage<0>(vr, tc[10]);
        vstage<1>(vr, tc[9]);
        vstage<2>(vr, tc[8]);
        vstage<3>(vr, tc[7]);
        vstage<4>(vr, esgn * tc[6]);   // e-swapped pairing on bit5 => R(-t)
        __syncthreads();               // all gathers done before rows are overwritten
#pragma unroll
        for (int a = 0; a < 16; ++a) {
            float x, y; upk2(vr[a], x, y);
            B0[(2 * a) * PITCH]     = x;
            B0[(2 * a + 1) * PITCH] = y;
        }
#pragma unroll
        for (int a = 16; a < 32; ++a) {
            float x, y; upk2(vr[a], x, y);
            B1[(2 * a - 32) * PITCH] = x;
            B1[(2 * a - 31) * PITCH] = y;
        }
        __syncthreads();

        // ===== pass 2: linear in-place, RY qubits 5..0 =====
        // fold q5 (component, scalar on fresh loads) and q4 (packed) into the load
        u64 vp[32];
        {
            float t5 = tc[5], t4 = tc[4];
            u64 tn4 = pk2(-t4, -t4), tp4 = pk2(t4, t4);
#pragma unroll
            for (int g = 0; g < 16; ++g) {
                float4 f = *reinterpret_cast<const float4*>(pld + 4 * g);
                float a0 = fmaf(-t5, f.y, f.x);
                float a1 = fmaf( t5, f.x, f.y);
                float b0 = fmaf(-t5, f.w, f.z);
                float b1 = fmaf( t5, f.z, f.w);
                u64 lo = pk2(a0, a1), hi = pk2(b0, b1);
                vp[2 * g]     = ffma2(tn4, hi, lo);   // q4 across i7
                vp[2 * g + 1] = ffma2(tp4, lo, hi);
            }
        }
        vstage<1>(vp, tc[3]);
        vstage<2>(vp, tc[2]);
        vstage<3>(vp, tc[1]);
        vstage<4>(vp, tc[0]);

        if (L < 19) {
#pragma unroll
            for (int g = 0; g < 16; ++g) {
                float x0, y0, x1, y1;
                upk2(vp[2 * g], x0, y0);
                upk2(vp[2 * g + 1], x1, y1);
                *reinterpret_cast<float4*>(pld + 4 * g) = make_float4(x0, y0, x1, y1);
            }
            __syncthreads();
        } else {
            // ===== expvals from registers =====
            // component = i6 (q5); pair bits b0..b4 = i7..i11 (q4..q0); u = i0..i5 (q11..q6)
            float S = 0.f, Ty = 0.f, T0 = 0.f, T1 = 0.f, T2 = 0.f, T3 = 0.f, T4 = 0.f;
#pragma unroll
            for (int a = 0; a < 32; ++a) {
                float x, y; upk2(vp[a], x, y);
                float px = x * x, py = y * y, ps = px + py;
                S += ps; Ty += py;
                if (a & 1)  T0 += ps;
                if (a & 2)  T1 += ps;
                if (a & 4)  T2 += ps;
                if (a & 8)  T3 += ps;
                if (a & 16) T4 += ps;
            }
            float val[12];
            val[0] = S - 2.f * T4;
            val[1] = S - 2.f * T3;
            val[2] = S - 2.f * T2;
            val[3] = S - 2.f * T1;
            val[4] = S - 2.f * T0;
            val[5] = S - 2.f * Ty;
#pragma unroll
            for (int q = 6; q < 12; ++q)
                val[q] = ((u >> (11 - q)) & 1) ? -S : S;
#pragma unroll
            for (int q = 0; q < 12; ++q) {
#pragma unroll
                for (int o = 16; o; o >>= 1)
                    val[q] += __shfl_xor_sync(~0u, val[q], o);
            }
            if (lane == 0) {
#pragma unroll
                for (int q = 0; q < 12; ++q) rsum[u >> 5][q] = val[q];
            }
        }
    }

    __syncthreads();
    if (u < 12) {
        out[(size_t)b * 12 + u] = (rsum[0][u] + rsum[1][u]) * oscale_s;
    }
}

extern "C" void kernel_launch(void* const* d_in, const int* in_sizes, int n_in,
                              void* d_out, int out_size) {
    const float* feats = (const float*)d_in[0];
    const float* qp    = (const float*)d_in[1];
    float* out         = (float*)d_out;
    qsim_kernel<<<4096, NT>>>(feats, qp, out);
}

// round 11
// speedup vs baseline: 1.0481x; 1.0080x over previous
#include <cuda_runtime.h>

#define NT 64
typedef unsigned long long u64;

__device__ __forceinline__ u64 pk2(float x, float y) {
    u64 r; asm("mov.b64 %0,{%1,%2};" : "=l"(r) : "f"(x), "f"(y)); return r;
}
__device__ __forceinline__ void upk2(u64 v, float& x, float& y) {
    asm("mov.b64 {%0,%1},%2;" : "=f"(x), "=f"(y) : "l"(v));
}
__device__ __forceinline__ u64 ffma2(u64 a, u64 b, u64 c) {
    u64 d; asm("fma.rn.f32x2 %0,%1,%2,%3;" : "=l"(d) : "l"(a), "l"(b), "l"(c)); return d;
}

// packed butterfly over pair-index bit B
template <int B>
__device__ __forceinline__ void vstage(u64* v, float t) {
    u64 tp = pk2(t, t), tn = pk2(-t, -t);
#pragma unroll
    for (int a = 0; a < 32; ++a)
        if (!(a & (1 << B))) {
            u64 A = v[a], Bv = v[a | (1 << B)];
            v[a]            = ffma2(tn, Bv, A);
            v[a | (1 << B)] = ffma2(tp, A, Bv);
        }
}

// register-pair index for pass-1 load row-pair q: a = (f0^{-1}(2q)) >> 1
__device__ __forceinline__ constexpr int AQ(int q) {
    int q0 = q & 1, q1 = (q >> 1) & 1, q2 = (q >> 2) & 1, q3 = (q >> 3) & 1, q4 = (q >> 4) & 1;
    return (q0 ^ q1 ^ q2) | ((q1 ^ q2) << 1) | ((q2 ^ q3 ^ q4) << 2)
         | ((q3 ^ q4) << 3) | (q4 << 4);
}

#define PITCH 68

__global__ void __launch_bounds__(NT, 11)
qsim_kernel(const float* __restrict__ feats,
            const float* __restrict__ qp,
            float* __restrict__ out)
{
    // layout T: element (i_lo, i_hi) at i_lo*PITCH + i_hi  (pad 68 -> bank rot by 4/row)
    __shared__ float buf[64 * PITCH];
    __shared__ float tt[240];
    __shared__ float wred[2], gred[2];
    __shared__ float oscale_s;
    __shared__ float rsum[2][12];

    const int u    = threadIdx.x;   // 0..63
    const int lane = u & 31;
    const int b    = blockIdx.x;

    // tan table + global cos product (cos factors -> output scale G^2)
    float gpart = 1.0f;
    for (int i = u; i < 240; i += NT) {
        float s, c; sincosf(0.5f * qp[12 + i], &s, &c);
        tt[i] = s / c; gpart *= c;
    }
#pragma unroll
    for (int o = 16; o; o >>= 1) gpart *= __shfl_xor_sync(~0u, gpart, o);
    if (lane == 0) gred[u >> 5] = gpart;

    // embedding: raw state into T layout (elem s at (s&63)*PITCH + (s>>6))
    const float2* f2 = reinterpret_cast<const float2*>(feats + (size_t)b * 2048);
    const float PIO2 = 1.5707963267948966f;
    float acc = 8.0f;
#pragma unroll
    for (int v = 0; v < 16; ++v) {
        int p = v * 64 + u;
        float2 x = f2[p];
        float y0 = tanhf(x.x) * PIO2;
        float y1 = tanhf(x.y) * PIO2;
        acc += y0 * y0 + y1 * y1;
        int s = 2 * p;
        buf[(s & 63) * PITCH + (s >> 6)]       = y0;
        buf[((s + 1) & 63) * PITCH + (s >> 6)] = y1;
    }
#pragma unroll
    for (int v = 16; v < 32; ++v) {
        int s = 2 * (v * 64 + u);
        buf[(s & 63) * PITCH + (s >> 6)]       = 0.5f;
        buf[((s + 1) & 63) * PITCH + (s >> 6)] = 0.5f;
    }
#pragma unroll
    for (int o = 16; o; o >>= 1) acc += __shfl_xor_sync(~0u, acc, o);
    if (lane == 0) wred[u >> 5] = acc;
    __syncthreads();
    if (u == 0) {
        float G = gred[0] * gred[1];
        oscale_s = (G * G) / (wred[0] + wred[1]);
    }

    // per-thread constants
    // i_hi = H(u) = Mhi^{-1}(u)
    int u0 = u & 1, u1 = (u >> 1) & 1, u2b = (u >> 2) & 1;
    int u3 = (u >> 3) & 1, u4 = (u >> 4) & 1, u5 = (u >> 5) & 1;
    int Hh = (u0 ^ u1) | ((u1 ^ u2b ^ u3) << 1) | ((u2b ^ u3) << 2)
           | ((u3 ^ u4 ^ u5) << 3) | ((u4 ^ u5) << 4) | (u5 << 5);
    int e = u0 ^ u1;                         // i6 of this thread's dst block
    const float* pL = buf + u;               // pass-1 load base (col u, + m*PITCH imm)
    float* B0 = buf + Hh + (e ? 32 * PITCH : 0);   // pass-1 store, rows 0..31
    float* B1 = buf + Hh + (e ? 0 : 32 * PITCH);   // pass-1 store, rows 32..63
    float* pld = buf + u * PITCH;            // pass-2 base (in-place)
    float esgn = e ? -1.0f : 1.0f;

#pragma unroll 1
    for (int L = 0; L < 20; ++L) {
        const float* tc = &tt[L * 12];

        // ===== pass 1: entangling gather (addressing-free) + RY qubits 11..6 =====
        u64 vr[32];
        {
            float t11 = tc[11];
            u64 tm = pk2(-t11, t11);
#pragma unroll
            for (int q = 0; q < 32; ++q) {
                float A = pL[(2 * q) * PITCH];
                float Bv = pL[(2 * q + 1) * PITCH];
                u64 ab = pk2(A, Bv), ba = pk2(Bv, A);
                // role: even row holds comp0 iff (q&1)==0
                vr[AQ(q)] = (q & 1) ? ffma2(tm, ab, ba) : ffma2(tm, ba, ab);
            }
        }
        vstage<0>(vr, tc[10]);
        vstage<1>(vr, tc[9]);
        vstage<2>(vr, tc[8]);
        vstage<3>(vr, tc[7]);
        vstage<4>(vr, esgn * tc[6]);   // e-swapped pairing on bit5 => R(-t)
        __syncthreads();               // all gathers done before rows are overwritten
#pragma unroll
        for (int a = 0; a < 16; ++a) {
            float x, y; upk2(vr[a], x, y);
            B0[(2 * a) * PITCH]     = x;
            B0[(2 * a + 1) * PITCH] = y;
        }
#pragma unroll
        for (int a = 16; a < 32; ++a) {
            float x, y; upk2(vr[a], x, y);
            B1[(2 * a - 32) * PITCH] = x;
            B1[(2 * a - 31) * PITCH] = y;
        }
        __syncthreads();

        // ===== pass 2: linear in-place, RY qubits 5..0 =====
        // fold q5 (component, scalar on fresh loads) and q4 (packed) into the load
        u64 vp[32];
        {
            float t5 = tc[5], t4 = tc[4];
            u64 tn4 = pk2(-t4, -t4), tp4 = pk2(t4, t4);
#pragma unroll
            for (int g = 0; g < 16; ++g) {
                float4 f = *reinterpret_cast<const float4*>(pld + 4 * g);
                float a0 = fmaf(-t5, f.y, f.x);
                float a1 = fmaf( t5, f.x, f.y);
                float b0 = fmaf(-t5, f.w, f.z);
                float b1 = fmaf( t5, f.z, f.w);
                u64 lo = pk2(a0, a1), hi = pk2(b0, b1);
                vp[2 * g]     = ffma2(tn4, hi, lo);   // q4 across i7
                vp[2 * g + 1] = ffma2(tp4, lo, hi);
            }
        }
        vstage<1>(vp, tc[3]);
        vstage<2>(vp, tc[2]);
        vstage<3>(vp, tc[1]);
        vstage<4>(vp, tc[0]);

        if (L < 19) {
#pragma unroll
            for (int g = 0; g < 16; ++g) {
                float x0, y0, x1, y1;
                upk2(vp[2 * g], x0, y0);
                upk2(vp[2 * g + 1], x1, y1);
                *reinterpret_cast<float4*>(pld + 4 * g) = make_float4(x0, y0, x1, y1);
            }
            __syncthreads();
        } else {
            // ===== expvals from registers =====
            // component = i6 (q5); pair bits b0..b4 = i7..i11 (q4..q0); u = i0..i5 (q11..q6)
            float S = 0.f, Ty = 0.f, T0 = 0.f, T1 = 0.f, T2 = 0.f, T3 = 0.f, T4 = 0.f;
#pragma unroll
            for (int a = 0; a < 32; ++a) {
                float x, y; upk2(vp[a], x, y);
                float px = x * x, py = y * y, ps = px + py;
                S += ps; Ty += py;
                if (a & 1)  T0 += ps;
                if (a & 2)  T1 += ps;
                if (a & 4)  T2 += ps;
                if (a & 8)  T3 += ps;
                if (a & 16) T4 += ps;
            }
            float val[12];
            val[0] = S - 2.f * T4;
            val[1] = S - 2.f * T3;
            val[2] = S - 2.f * T2;
            val[3] = S - 2.f * T1;
            val[4] = S - 2.f * T0;
            val[5] = S - 2.f * Ty;
#pragma unroll
            for (int q = 6; q < 12; ++q)
                val[q] = ((u >> (11 - q)) & 1) ? -S : S;
#pragma unroll
            for (int q = 0; q < 12; ++q) {
#pragma unroll
                for (int o = 16; o; o >>= 1)
                    val[q] += __shfl_xor_sync(~0u, val[q], o);
            }
            if (lane == 0) {
#pragma unroll
                for (int q = 0; q < 12; ++q) rsum[u >> 5][q] = val[q];
            }
        }
    }

    __syncthreads();
    if (u < 12) {
        out[(size_t)b * 12 + u] = (rsum[0][u] + rsum[1][u]) * oscale_s;
    }
}

extern "C" void kernel_launch(void* const* d_in, const int* in_sizes, int n_in,
                              void* d_out, int out_size) {
    const float* feats = (const float*)d_in[0];
    const float* qp    = (const float*)d_in[1];
    float* out         = (float*)d_out;
    qsim_kernel<<<4096, NT>>>(feats, qp, out);
}